// round 3
// baseline (speedup 1.0000x reference)
#include <cuda_runtime.h>
#include <math.h>

#define NPT   8192
#define CC    128
#define PP    1024
#define KMAX  64

// scratch (device globals; no allocations allowed)
__device__ float g_Asrc[NPT*CC];
__device__ float g_Adst[NPT*CC];
__device__ float g_V[NPT*CC];
__device__ int   g_idx[NPT*KMAX];
__device__ int   g_cnt[NPT];

// ---------------------------------------------------------------------------
// Kernel A: three GEMMs  x[8192,128] @ {w_lin,w_src,w_dst}[128,128]
// grid (512, 3), block 128.  16 rows per block, transposed x tile in smem.
// ---------------------------------------------------------------------------
__global__ __launch_bounds__(128)
void gemm3_kernel(const float* __restrict__ x,
                  const float* __restrict__ w_lin,
                  const float* __restrict__ w_src,
                  const float* __restrict__ w_dst)
{
    const int c    = threadIdx.x;
    const int row0 = blockIdx.x * 16;

    const float* W; float* O;
    if (blockIdx.y == 0)      { W = w_lin; O = g_V;    }
    else if (blockIdx.y == 1) { W = w_src; O = g_Asrc; }
    else                      { W = w_dst; O = g_Adst; }

    // xs[r][ii] = x[row0+ii][r], padded stride 20 floats (float4-aligned)
    __shared__ __align__(16) float xs[128 * 20];
    #pragma unroll
    for (int ii = 0; ii < 16; ii++)
        xs[c * 20 + ii] = x[(row0 + ii) * CC + c];
    __syncthreads();

    float acc[16];
    #pragma unroll
    for (int q = 0; q < 16; q++) acc[q] = 0.f;

    const float* wc = W + c;
    #pragma unroll 4
    for (int r = 0; r < 128; r++) {
        float w = wc[r * CC];
        const float* xr = &xs[r * 20];
        #pragma unroll
        for (int q = 0; q < 16; q += 4) {
            float4 p = *(const float4*)(xr + q);
            acc[q]     = fmaf(p.x, w, acc[q]);
            acc[q + 1] = fmaf(p.y, w, acc[q + 1]);
            acc[q + 2] = fmaf(p.z, w, acc[q + 2]);
            acc[q + 3] = fmaf(p.w, w, acc[q + 3]);
        }
    }
    #pragma unroll
    for (int ii = 0; ii < 16; ii++)
        O[(row0 + ii) * CC + c] = acc[ii];
}

// ---------------------------------------------------------------------------
// Kernel B: radius + nearest-K neighbor selection. One block per target.
// Effective set = { j : d2 <= min(64th smallest d2, R^2) }  (<= 64 members).
// Deterministic ordered compaction (ascending j) via ballot prefix sums.
// ---------------------------------------------------------------------------
__global__ __launch_bounds__(128)
void neigh_kernel(const float* __restrict__ pos)
{
    const int i     = blockIdx.x;
    const int t     = threadIdx.x;         // 128 threads, 8 candidates each
    const int lane  = t & 31;
    const int wid   = t >> 5;
    const int cbase = (i >> 10) << 10;     // cloud base point index

    __shared__ int   red[4];
    __shared__ float pi[3];
    if (t < 3) pi[t] = pos[i * 3 + t];
    __syncthreads();
    const float px = pi[0], py = pi[1], pz = pi[2];

    unsigned bits[8];
    #pragma unroll
    for (int q = 0; q < 8; q++) {
        int j = q * 128 + t;
        const float* pj = pos + (size_t)(cbase + j) * 3;
        float dx = px - pj[0];
        float dy = py - pj[1];
        float dz = pz - pj[2];
        float d2 = dx * dx + dy * dy + dz * dz;
        bits[q] = __float_as_uint(d2);     // non-negative floats: bit order == value order
    }

    const unsigned R2b = __float_as_uint(0.04f);

    // count within radius
    int local = 0;
    #pragma unroll
    for (int q = 0; q < 8; q++) local += (bits[q] <= R2b);
    #pragma unroll
    for (int o = 16; o > 0; o >>= 1) local += __shfl_down_sync(0xffffffffu, local, o);
    if (lane == 0) red[wid] = local;
    __syncthreads();
    int total = red[0] + red[1] + red[2] + red[3];
    __syncthreads();

    unsigned th = R2b;
    if (total > KMAX) {
        // rare path: bit-level binary search for the 64th smallest distance
        unsigned lo = 0, hi = R2b;
        while (lo < hi) {
            unsigned mid = lo + ((hi - lo) >> 1);
            int cnt = 0;
            #pragma unroll
            for (int q = 0; q < 8; q++) cnt += (bits[q] <= mid);
            #pragma unroll
            for (int o = 16; o > 0; o >>= 1) cnt += __shfl_down_sync(0xffffffffu, cnt, o);
            if (lane == 0) red[wid] = cnt;
            __syncthreads();
            int tot = red[0] + red[1] + red[2] + red[3];
            __syncthreads();
            if (tot >= KMAX) hi = mid; else lo = mid + 1;
        }
        th = lo;
    }

    // ordered compaction: j = q*128 + t ascending over (q, t)
    int wbase = 0;
    for (int q = 0; q < 8; q++) {
        bool sel = (bits[q] <= th);
        unsigned ball = __ballot_sync(0xffffffffu, sel);
        if (lane == 0) red[wid] = __popc(ball);
        __syncthreads();
        int woff = 0;
        #pragma unroll
        for (int w = 0; w < 4; w++) if (w < wid) woff += red[w];
        int tot = red[0] + red[1] + red[2] + red[3];
        int rank = wbase + woff + __popc(ball & ((1u << lane) - 1u));
        if (sel && rank < KMAX) g_idx[i * KMAX + rank] = q * 128 + t;
        wbase += tot;
        __syncthreads();
    }
    if (t == 0) g_cnt[i] = (wbase < KMAX) ? wbase : KMAX;
}

// ---------------------------------------------------------------------------
// Kernel C: fused delta / attention GEMM / softmax / aggregate.
// One block per target, 128 threads (thread == output channel).
// Neighbors processed in chunks of 32 staged in shared memory.
// ---------------------------------------------------------------------------
#define CHK 32

__global__ __launch_bounds__(128)
void main_kernel(const float* __restrict__ pos,
                 const float* __restrict__ nrm,
                 const float* __restrict__ w_pos,
                 const float* __restrict__ b_pos,
                 const float* __restrict__ pos_gamma,
                 const float* __restrict__ pos_beta,
                 const float* __restrict__ pos_mean,
                 const float* __restrict__ pos_var,
                 const float* __restrict__ w_attn,
                 const float* __restrict__ b_attn,
                 const float* __restrict__ attn_gamma,
                 const float* __restrict__ attn_beta,
                 const float* __restrict__ attn_mean,
                 const float* __restrict__ attn_var,
                 float* __restrict__ out)
{
    __shared__ __align__(16) float pre_s[CHK * CC];   // 16 KB
    __shared__ __align__(16) float vd_s [CHK * CC];   // 16 KB
    __shared__ __align__(16) float rel_s[KMAX * 8];   //  2 KB
    __shared__ int   idx_s[KMAX];
    __shared__ float pi6[6];

    const int i     = blockIdx.x;
    const int c     = threadIdx.x;
    const int cbase = (i >> 10) << 10;
    const int m     = g_cnt[i];

    if (c < 6)    pi6[c]  = (c < 3) ? pos[i * 3 + c] : nrm[i * 3 + c - 3];
    if (c < KMAX) idx_s[c] = (c < m) ? g_idx[i * KMAX + c] : 0;
    __syncthreads();

    if (c < KMAX && c < m) {
        int gj = cbase + idx_s[c];
        rel_s[c * 8 + 0] = pi6[0] - pos[gj * 3 + 0];
        rel_s[c * 8 + 1] = pi6[1] - pos[gj * 3 + 1];
        rel_s[c * 8 + 2] = pi6[2] - pos[gj * 3 + 2];
        rel_s[c * 8 + 3] = pi6[3] - nrm[gj * 3 + 0];
        rel_s[c * 8 + 4] = pi6[4] - nrm[gj * 3 + 1];
        rel_s[c * 8 + 5] = pi6[5] - nrm[gj * 3 + 2];
    }

    // fold BatchNorms into per-channel affines
    const float sp = rsqrtf(pos_var[c]  + 1e-5f) * pos_gamma[c];
    const float bp = (b_pos[c]  - pos_mean[c])  * sp + pos_beta[c];
    const float sa = rsqrtf(attn_var[c] + 1e-5f) * attn_gamma[c];
    const float ba = (b_attn[c] - attn_mean[c]) * sa + attn_beta[c];
    float wpf[6];
    #pragma unroll
    for (int r = 0; r < 6; r++) wpf[r] = w_pos[r * CC + c] * sp;
    const float ad = g_Adst[i * CC + c];

    float fsum = 0.f, facc = 0.f;
    const float* wc = w_attn + c;

    for (int k0 = 0; k0 < m; k0 += CHK) {
        const int kn = min(CHK, m - k0);
        __syncthreads();   // protect pre_s/vd_s reuse (also covers rel_s init)

        // phase 1: delta + pre + (v + delta) for this chunk
        for (int k = 0; k < kn; k++) {
            const float* rl = &rel_s[(k0 + k) * 8];
            float d = bp;
            #pragma unroll
            for (int r = 0; r < 6; r++) d = fmaf(rl[r], wpf[r], d);
            d = fmaxf(d, 0.f);
            int gj = cbase + idx_s[k0 + k];
            pre_s[k * CC + c] = ad - g_Asrc[(size_t)gj * CC + c] + d;
            vd_s [k * CC + c] = g_V  [(size_t)gj * CC + c] + d;
        }
        __syncthreads();

        // phase 2: alpha = relu(bn(pre @ w_attn)); exp-softmax accumulate.
        // alpha >= 0 (ReLU) => exp without max subtraction is safe.
        const int nt = (kn + 15) >> 4;
        for (int kt = 0; kt < nt; kt++) {
            float acc[16];
            #pragma unroll
            for (int q = 0; q < 16; q++) acc[q] = 0.f;

            const float* ps = pre_s + kt * 16 * CC;
            #pragma unroll 2
            for (int r = 0; r < 128; r += 4) {
                float w0 = wc[(r + 0) * CC];
                float w1 = wc[(r + 1) * CC];
                float w2 = wc[(r + 2) * CC];
                float w3 = wc[(r + 3) * CC];
                #pragma unroll
                for (int q = 0; q < 16; q++) {
                    float4 p = *(const float4*)(ps + q * CC + r);
                    float a = acc[q];
                    a = fmaf(p.x, w0, a);
                    a = fmaf(p.y, w1, a);
                    a = fmaf(p.z, w2, a);
                    a = fmaf(p.w, w3, a);
                    acc[q] = a;
                }
            }
            const int kb = kt * 16;
            #pragma unroll
            for (int q = 0; q < 16; q++) {
                int k = kb + q;
                if (k < kn) {
                    float alpha = fmaxf(fmaf(acc[q], sa, ba), 0.f);
                    float e = __expf(alpha);
                    fsum += e;
                    facc = fmaf(e, vd_s[k * CC + c], facc);
                }
            }
        }
    }
    out[i * CC + c] = facc / fsum;
}

// ---------------------------------------------------------------------------
extern "C" void kernel_launch(void* const* d_in, const int* in_sizes, int n_in,
                              void* d_out, int out_size)
{
    const float* x      = (const float*)d_in[0];
    const float* pos    = (const float*)d_in[1];
    const float* nrm    = (const float*)d_in[2];
    // d_in[3] = batch (structured, unused)
    const float* w_lin  = (const float*)d_in[4];
    const float* w_src  = (const float*)d_in[5];
    const float* w_dst  = (const float*)d_in[6];
    const float* w_pos  = (const float*)d_in[7];
    const float* b_pos  = (const float*)d_in[8];
    const float* pos_g  = (const float*)d_in[9];
    const float* pos_b  = (const float*)d_in[10];
    const float* pos_m  = (const float*)d_in[11];
    const float* pos_v  = (const float*)d_in[12];
    const float* w_attn = (const float*)d_in[13];
    const float* b_attn = (const float*)d_in[14];
    const float* attn_g = (const float*)d_in[15];
    const float* attn_b = (const float*)d_in[16];
    const float* attn_m = (const float*)d_in[17];
    const float* attn_v = (const float*)d_in[18];
    float* out = (float*)d_out;

    gemm3_kernel<<<dim3(512, 3, 1), 128>>>(x, w_lin, w_src, w_dst);
    neigh_kernel<<<NPT, 128>>>(pos);
    main_kernel<<<NPT, 128>>>(pos, nrm, w_pos, b_pos, pos_g, pos_b, pos_m, pos_v,
                              w_attn, b_attn, attn_g, attn_b, attn_m, attn_v, out);
}